// round 15
// baseline (speedup 1.0000x reference)
#include <cuda_runtime.h>

// Problem constants (fixed shapes from reference)
#define Bn  4
#define Cn  128
#define Hn  64
#define Wn  64
#define Ln  16
#define Kn  64
#define CDn 8
#define HW  (Hn * Wn)

typedef unsigned long long u64;

// ---- packed f32x2 helpers ----
__device__ __forceinline__ u64 pack2(float x, float y) {
    u64 r; asm("mov.b64 %0, {%1, %2};" : "=l"(r) : "f"(x), "f"(y)); return r;
}
__device__ __forceinline__ void unpack2(u64 v, float& x, float& y) {
    asm("mov.b64 {%0, %1}, %2;" : "=f"(x), "=f"(y) : "l"(v));
}
__device__ __forceinline__ u64 add2(u64 a, u64 b) {
    u64 d; asm("add.rn.f32x2 %0, %1, %2;" : "=l"(d) : "l"(a), "l"(b)); return d;
}
__device__ __forceinline__ u64 fma2(u64 a, u64 b, u64 c) {
    u64 d; asm("fma.rn.f32x2 %0, %1, %2, %3;" : "=l"(d) : "l"(a), "l"(b), "l"(c)); return d;
}
__device__ __forceinline__ u64 mul2(u64 a, u64 b) {
    u64 d; asm("mul.rn.f32x2 %0, %1, %2;" : "=l"(d) : "l"(a), "l"(b)); return d;
}

// Champion (R4/R6) with PIXEL-PAIR lane packing:
//   lane0 = pixel h0, lane1 = pixel h0+1, packed per dim j.
//   One 16-op f32x2 chain per code yields BOTH pixels' exact diff-form
//   distances in the two lanes -> no cross-lane FADD, no pack/unpack MOVs
//   in the loop (codes pre-duplicated {-c,-c} in smem; lane extraction is
//   register aliasing). Tracking: FMNMX best + pred-off-chain SEL index
//   (strict <, first-k-wins) — exact, no guard needed.
__global__ __launch_bounds__(128) void vq_kernel(
    const float* __restrict__ z,      // (B, C, H, W)
    const float* __restrict__ codes,  // (L, K, CD)
    float* __restrict__ qout,         // (B, C, H, W) or null
    float* __restrict__ idxf,         // (B, H, W, L) as float or null
    int*   __restrict__ idxi)         // (B, H, W, L) as int or null
{
    // Duplicated negated codes: cd[(ls*Kn + k)*8 + j] = {-c_j, -c_j}
    __shared__ __align__(16) u64 cd[2 * Kn * CDn];   // 8 KB

    const int tid = threadIdx.y * 64 + threadIdx.x;
    const int l0  = blockIdx.x * 2;

    // Pre-pack: thread tid owns one (l-sub, code) of the 128 entries.
    {
        const float4 va = reinterpret_cast<const float4*>(
            codes + (l0 * Kn + tid) * CDn)[0];
        const float4 vb = reinterpret_cast<const float4*>(
            codes + (l0 * Kn + tid) * CDn)[1];
        u64* e = cd + tid * CDn;
        e[0] = pack2(-va.x, -va.x);
        e[1] = pack2(-va.y, -va.y);
        e[2] = pack2(-va.z, -va.z);
        e[3] = pack2(-va.w, -va.w);
        e[4] = pack2(-vb.x, -vb.x);
        e[5] = pack2(-vb.y, -vb.y);
        e[6] = pack2(-vb.z, -vb.z);
        e[7] = pack2(-vb.w, -vb.w);
    }
    __syncthreads();

    const int w  = threadIdx.x;
    const int ls = threadIdx.y;
    const int l  = l0 + ls;
    const int h0 = blockIdx.y * 2;
    const int b  = blockIdx.z;

    // z packed per dim across the two pixels: zz[j] = {z_j(h0), z_j(h0+1)}
    u64 zz[8];
    {
        const float* zb = z + ((b * Cn + l * CDn) * Hn + h0) * Wn + w;
        #pragma unroll
        for (int j = 0; j < 8; j++)
            zz[j] = pack2(zb[j * HW], zb[j * HW + Wn]);
    }

    const ulonglong2* __restrict__ cb =
        reinterpret_cast<const ulonglong2*>(cd + ls * Kn * CDn);

    float best0 = 3.4e38f, best1 = 3.4e38f;
    int   bi0 = 0, bi1 = 0;

    #pragma unroll 8
    for (int k = 0; k < Kn; k++) {
        const ulonglong2 q0 = cb[4 * k + 0];   // dims 0,1
        const ulonglong2 q1 = cb[4 * k + 1];   // dims 2,3
        const ulonglong2 q2 = cb[4 * k + 2];   // dims 4,5
        const ulonglong2 q3 = cb[4 * k + 3];   // dims 6,7
        u64 t, d;
        t = add2(zz[0], q0.x); d = mul2(t, t);
        t = add2(zz[1], q0.y); d = fma2(t, t, d);
        t = add2(zz[2], q1.x); d = fma2(t, t, d);
        t = add2(zz[3], q1.y); d = fma2(t, t, d);
        t = add2(zz[4], q2.x); d = fma2(t, t, d);
        t = add2(zz[5], q2.y); d = fma2(t, t, d);
        t = add2(zz[6], q3.x); d = fma2(t, t, d);
        t = add2(zz[7], q3.y); d = fma2(t, t, d);
        float d0, d1; unpack2(d, d0, d1);      // register aliasing, no math
        // exact tracking: FMNMX chain + pred-off-chain index select
        const float o0 = best0;
        best0 = fminf(o0, d0);
        bi0   = (d0 < o0) ? k : bi0;           // strict <: first k wins ties
        const float o1 = best1;
        best1 = fminf(o1, d1);
        bi1   = (d1 < o1) ? k : bi1;
    }

    // ---- Outputs (codes recovered from the lo lane of cd: value = -lo) ----
    const float* __restrict__ cneg =
        reinterpret_cast<const float*>(cd + ls * Kn * CDn);
    #pragma unroll
    for (int px = 0; px < 2; px++) {
        const int kb = px ? bi1 : bi0;
        const int h  = h0 + px;
        if (qout) {
            float* qb = qout + ((b * Cn + l * CDn) * Hn + h) * Wn + w;
            #pragma unroll
            for (int j = 0; j < 8; j++)
                qb[j * HW] = -cneg[(kb * CDn + j) * 2];   // lo lane of u64
        }
        const long long io = (((long long)b * Hn + h) * Wn + w) * Ln + l;
        if (idxf) idxf[io] = (float)kb;
        if (idxi) idxi[io] = kb;
    }
}

extern "C" void kernel_launch(void* const* d_in, const int* in_sizes, int n_in,
                              void* d_out, int out_size)
{
    const float* z     = (const float*)d_in[0];
    const float* codes = (const float*)d_in[1];
    // Defensive: if input order is (codes, z), swap by element count.
    if (n_in >= 2 && in_sizes[0] == Ln * Kn * CDn && in_sizes[1] == Bn * Cn * HW) {
        codes = (const float*)d_in[0];
        z     = (const float*)d_in[1];
    }

    const int NQ = Bn * Cn * HW;       // 2097152
    const int NI = Bn * HW * Ln;       // 262144

    float* qout = nullptr;
    float* idxf = nullptr;
    int*   idxi = nullptr;

    if (out_size >= NQ + NI) {           // both outputs, flattened, float dtype
        qout = (float*)d_out;
        idxf = (float*)d_out + NQ;
    } else if (out_size == NI) {         // idx only -> int dtype
        idxi = (int*)d_out;
    } else {                             // quantized only
        qout = (float*)d_out;
    }

    dim3 grid(Ln / 2, Hn / 2, Bn);   // (8, 32, 4) = 1024 blocks
    dim3 block(64, 2, 1);            // 128 threads
    vq_kernel<<<grid, block>>>(z, codes, qout, idxf, idxi);
}

// round 16
// speedup vs baseline: 1.2262x; 1.2262x over previous
#include <cuda_runtime.h>

// Problem constants (fixed shapes from reference)
#define Bn  4
#define Cn  128
#define Hn  64
#define Wn  64
#define Ln  16
#define Kn  64
#define CDn 8
#define HW  (Hn * Wn)

typedef unsigned long long u64;

// ---- packed f32x2 helpers ----
__device__ __forceinline__ u64 pack2(float x, float y) {
    u64 r; asm("mov.b64 %0, {%1, %2};" : "=l"(r) : "f"(x), "f"(y)); return r;
}
__device__ __forceinline__ void unpack2(u64 v, float& x, float& y) {
    asm("mov.b64 {%0, %1}, %2;" : "=f"(x), "=f"(y) : "l"(v));
}
__device__ __forceinline__ u64 add2(u64 a, u64 b) {
    u64 d; asm("add.rn.f32x2 %0, %1, %2;" : "=l"(d) : "l"(a), "l"(b)); return d;
}
__device__ __forceinline__ u64 fma2(u64 a, u64 b, u64 c) {
    u64 d; asm("fma.rn.f32x2 %0, %1, %2, %3;" : "=l"(d) : "l"(a), "l"(b), "l"(c)); return d;
}
__device__ __forceinline__ u64 mul2(u64 a, u64 b) {
    u64 d; asm("mul.rn.f32x2 %0, %1, %2;" : "=l"(d) : "l"(a), "l"(b)); return d;
}

// R4 champion structure + pre-packed u64 code table (kills the 4 pack2 MOVs
// per code per tracker that served no math).
//  - One thread: one (b, l, w) at TWO pixels (h0, h0+1); each warp has a
//    single l -> all code smem reads broadcast; 2 LDS.128 per code serve
//    both pixels.
//  - Codes in smem as u64 dim-pairs {-c2i, -c2i+1}, 4 per code (32B stride);
//    the float view of this table IS the negated-code table (outputs read it
//    directly).
//  - Two independent trackers (k in [0,32), [32,64)); per pixel:
//    best = fminf(best, dist) (FMNMX chain), bi = (dist < best_old) ? k : bi
//    (SEL off-chain). Strict <, first-k-wins == reference argmin. Exact math.
__global__ __launch_bounds__(128) void vq_kernel(
    const float* __restrict__ z,      // (B, C, H, W)
    const float* __restrict__ codes,  // (L, K, CD)
    float* __restrict__ qout,         // (B, C, H, W) or null
    float* __restrict__ idxf,         // (B, H, W, L) as float or null
    int*   __restrict__ idxi)         // (B, H, W, L) as int or null
{
    // Packed negated codes: cpk[(ls*Kn + k)*4 + i] = {-c_2i, -c_2i+1}
    __shared__ __align__(16) u64 cpk[2 * Kn * 4];   // 4 KB

    const int tid = threadIdx.y * 64 + threadIdx.x;
    const int l0  = blockIdx.x * 2;

    // Pre-pack: thread tid owns one (l-sub, code) of the 128 entries.
    {
        const float4 va = reinterpret_cast<const float4*>(
            codes + (l0 * Kn + tid) * CDn)[0];
        const float4 vb = reinterpret_cast<const float4*>(
            codes + (l0 * Kn + tid) * CDn)[1];
        ulonglong2* e = reinterpret_cast<ulonglong2*>(cpk + tid * 4);
        e[0] = make_ulonglong2(pack2(-va.x, -va.y), pack2(-va.z, -va.w));
        e[1] = make_ulonglong2(pack2(-vb.x, -vb.y), pack2(-vb.z, -vb.w));
    }
    __syncthreads();

    const int w  = threadIdx.x;
    const int ls = threadIdx.y;
    const int l  = l0 + ls;
    const int h0 = blockIdx.y * 2;
    const int b  = blockIdx.z;

    // Load z for 2 pixels x 8 channels, packed by dim pairs per pixel.
    u64 zp[2][4];
    #pragma unroll
    for (int i = 0; i < 4; i++) {
        const float* p =
            z + (((b * Cn + l * CDn + 2 * i) * Hn + h0) * Wn + w);
        const float a0 = p[0];            // pixel0, dim 2i
        const float a1 = p[Wn];           // pixel1, dim 2i
        const float b0 = p[HW];           // pixel0, dim 2i+1
        const float b1 = p[HW + Wn];      // pixel1, dim 2i+1
        zp[0][i] = pack2(a0, b0);
        zp[1][i] = pack2(a1, b1);
    }

    const ulonglong2* __restrict__ cb =
        reinterpret_cast<const ulonglong2*>(cpk + ls * Kn * 4);

    float best[2][2] = {{3.4e38f, 3.4e38f}, {3.4e38f, 3.4e38f}};
    int   bi[2][2]   = {{0, 32}, {0, 32}};

    #pragma unroll
    for (int kk = 0; kk < 32; kk++) {
        #pragma unroll
        for (int t = 0; t < 2; t++) {          // tracker: k = kk + 32*t
            const int k = kk + 32 * t;
            const ulonglong2 v0 = cb[2 * k];       // dims 0-3  (LDS.128)
            const ulonglong2 v1 = cb[2 * k + 1];   // dims 4-7  (LDS.128)
            #pragma unroll
            for (int p = 0; p < 2; p++) {      // pixel
                u64 d, s;
                s = add2(zp[p][0], v0.x); d = mul2(s, s);
                s = add2(zp[p][1], v0.y); d = fma2(s, s, d);
                s = add2(zp[p][2], v1.x); d = fma2(s, s, d);
                s = add2(zp[p][3], v1.y); d = fma2(s, s, d);
                float dx, dy; unpack2(d, dx, dy);
                const float dist = dx + dy;
                // FMNMX chain + pred-selected index (strict <, first wins)
                const float bo = best[p][t];
                best[p][t] = fminf(bo, dist);
                bi[p][t]   = (dist < bo) ? k : bi[p][t];
            }
        }
    }

    // ---- Outputs (negated codes read straight from the packed table) ----
    const float* __restrict__ cneg =
        reinterpret_cast<const float*>(cpk + ls * Kn * 4);
    #pragma unroll
    for (int p = 0; p < 2; p++) {
        // Merge trackers: strict < keeps tracker 0 (lower k) on ties.
        const int kb = (best[p][1] < best[p][0]) ? bi[p][1] : bi[p][0];
        const int h  = h0 + p;
        if (qout) {
            #pragma unroll
            for (int j = 0; j < 8; j++) {
                const float v = -cneg[kb * CDn + j];
                qout[((b * Cn + l * CDn + j) * Hn + h) * Wn + w] = v;
            }
        }
        const long long io = (((long long)b * Hn + h) * Wn + w) * Ln + l;
        if (idxf) idxf[io] = (float)kb;
        if (idxi) idxi[io] = kb;
    }
}

extern "C" void kernel_launch(void* const* d_in, const int* in_sizes, int n_in,
                              void* d_out, int out_size)
{
    const float* z     = (const float*)d_in[0];
    const float* codes = (const float*)d_in[1];
    // Defensive: if input order is (codes, z), swap by element count.
    if (n_in >= 2 && in_sizes[0] == Ln * Kn * CDn && in_sizes[1] == Bn * Cn * HW) {
        codes = (const float*)d_in[0];
        z     = (const float*)d_in[1];
    }

    const int NQ = Bn * Cn * HW;       // 2097152
    const int NI = Bn * HW * Ln;       // 262144

    float* qout = nullptr;
    float* idxf = nullptr;
    int*   idxi = nullptr;

    if (out_size >= NQ + NI) {           // both outputs, flattened, float dtype
        qout = (float*)d_out;
        idxf = (float*)d_out + NQ;
    } else if (out_size == NI) {         // idx only -> int dtype
        idxi = (int*)d_out;
    } else {                             // quantized only
        qout = (float*)d_out;
    }

    dim3 grid(Ln / 2, Hn / 2, Bn);   // (8, 32, 4) = 1024 blocks
    dim3 block(64, 2, 1);            // 128 threads
    vq_kernel<<<grid, block>>>(z, codes, qout, idxf, idxi);
}